// round 2
// baseline (speedup 1.0000x reference)
#include <cuda_runtime.h>

#define VOCAB 100000
#define DIM   300
#define BATCH 65536
#define KNEG  10
#define NROWS (KNEG + 1)
#define NF4   75            // DIM/4 float4 per row
#define WARPS_PER_BLOCK 8
#define THREADS (WARPS_PER_BLOCK * 32)
#define NBLOCKS (BATCH / WARPS_PER_BLOCK)   // 8192

__device__ float g_partials[NBLOCKS];
__device__ unsigned int g_count;    // zero at load; last block resets each run

__device__ __forceinline__ float softplus_fast(float x) {
    // valid for |x| <= ~10 (inputs are clipped): log(1+exp(x))
    return __logf(1.0f + __expf(x));
}

__global__ __launch_bounds__(THREADS)
void sg_loss_kernel(const float* __restrict__ u_w,
                    const float* __restrict__ v_w,
                    const int*   __restrict__ pos_u,
                    const int*   __restrict__ pos_v,
                    const int*   __restrict__ neg_v,
                    float* __restrict__ out) {
    const int warp = threadIdx.x >> 5;
    const int lane = threadIdx.x & 31;
    const int b = blockIdx.x * WARPS_PER_BLOCK + warp;

    const bool has2 = lane < (NF4 - 64);   // lanes 0..10

    // ---- gather emb_u into registers (12 floats/lane) ----
    const float4* u_row = reinterpret_cast<const float4*>(u_w + (long long)pos_u[b] * DIM);
    const float4 u0 = u_row[lane];
    const float4 u1 = u_row[lane + 32];
    float4 u2 = make_float4(0.f, 0.f, 0.f, 0.f);
    if (has2) u2 = u_row[lane + 64];

    // ---- 11 v-row indices ----
    int vidx[NROWS];
    vidx[0] = pos_v[b];
#pragma unroll
    for (int k = 0; k < KNEG; k++) vidx[k + 1] = neg_v[b * KNEG + k];

    // ---- accumulate per-lane partial dots for all 11 rows (max MLP) ----
    float p[NROWS];
#pragma unroll
    for (int j = 0; j < NROWS; j++) {
        const float4* v_row = reinterpret_cast<const float4*>(v_w + (long long)vidx[j] * DIM);
        const float4 v0 = v_row[lane];
        const float4 v1 = v_row[lane + 32];
        float4 v2 = make_float4(0.f, 0.f, 0.f, 0.f);
        if (has2) v2 = v_row[lane + 64];

        float a = u0.x * v0.x;
        a = fmaf(u0.y, v0.y, a); a = fmaf(u0.z, v0.z, a); a = fmaf(u0.w, v0.w, a);
        float c = u1.x * v1.x;
        c = fmaf(u1.y, v1.y, c); c = fmaf(u1.z, v1.z, c); c = fmaf(u1.w, v1.w, c);
        float e = u2.x * v2.x;
        e = fmaf(u2.y, v2.y, e); e = fmaf(u2.z, v2.z, e); e = fmaf(u2.w, v2.w, e);
        p[j] = a + c + e;
    }

    // ---- butterfly-reduce all 11 dots with cross-value ILP ----
#pragma unroll
    for (int off = 16; off; off >>= 1) {
#pragma unroll
        for (int j = 0; j < NROWS; j++)
            p[j] += __shfl_xor_sync(0xffffffffu, p[j], off);
    }

    // all lanes hold full dots; compute loss redundantly (warp-uniform)
    float s0 = fminf(fmaxf(p[0], -10.f), 10.f);
    float loss = softplus_fast(-s0);                 // -log_sigmoid(score)
#pragma unroll
    for (int j = 1; j < NROWS; j++) {
        float s = fminf(fmaxf(p[j], -10.f), 10.f);
        loss += softplus_fast(s);                    // -log_sigmoid(-neg_score)
    }

    __shared__ float sloss[WARPS_PER_BLOCK];
    if (lane == 0) sloss[warp] = loss;
    __syncthreads();

    __shared__ unsigned s_is_last;
    if (threadIdx.x == 0) {
        float t = 0.f;
#pragma unroll
        for (int i = 0; i < WARPS_PER_BLOCK; i++) t += sloss[i];
        g_partials[blockIdx.x] = t;
        __threadfence();
        unsigned prev = atomicAdd(&g_count, 1u);
        s_is_last = (prev == (unsigned)(gridDim.x - 1));
    }
    __syncthreads();

    // ---- last block reduces all partials (deterministic fixed order) ----
    if (s_is_last) {
        __threadfence();
        const float4* pp = reinterpret_cast<const float4*>(g_partials);
        float t = 0.f;
#pragma unroll
        for (int i = 0; i < (NBLOCKS / 4) / THREADS; i++) {   // 8 float4 per thread
            float4 v = pp[threadIdx.x + i * THREADS];
            t += (v.x + v.y) + (v.z + v.w);
        }
#pragma unroll
        for (int off = 16; off; off >>= 1)
            t += __shfl_xor_sync(0xffffffffu, t, off);

        __shared__ float sred[WARPS_PER_BLOCK];
        if (lane == 0) sred[warp] = t;
        __syncthreads();
        if (threadIdx.x == 0) {
            float total = 0.f;
#pragma unroll
            for (int i = 0; i < WARPS_PER_BLOCK; i++) total += sred[i];
            out[0] = total * (1.0f / (float)BATCH);
            g_count = 0;   // reset for next graph replay
        }
    }
}

extern "C" void kernel_launch(void* const* d_in, const int* in_sizes, int n_in,
                              void* d_out, int out_size) {
    const float* u_w   = (const float*)d_in[0];
    const float* v_w   = (const float*)d_in[1];
    const int*   pos_u = (const int*)  d_in[2];
    const int*   pos_v = (const int*)  d_in[3];
    const int*   neg_v = (const int*)  d_in[4];
    float* out = (float*)d_out;

    sg_loss_kernel<<<NBLOCKS, THREADS>>>(u_w, v_w, pos_u, pos_v, neg_v, out);
}

// round 3
// speedup vs baseline: 1.4026x; 1.4026x over previous
#include <cuda_runtime.h>

#define VOCAB 100000
#define DIM   300
#define BATCH 65536
#define KNEG  10
#define NB0   6             // batch 0: rows 0..5 (row 0 = pos)
#define NB1   5             // batch 1: rows 6..10
#define NF4   75            // DIM/4 float4 per row
#define WARPS_PER_BLOCK 8
#define THREADS (WARPS_PER_BLOCK * 32)
#define NBLOCKS (BATCH / WARPS_PER_BLOCK)   // 8192

__device__ float g_partials[NBLOCKS];
__device__ unsigned int g_count;    // zero-init; last block resets after use

__device__ __forceinline__ float softplus_fast(float x) {
    // valid for clipped |x| <= 10
    return __logf(1.0f + __expf(x));
}

__device__ __forceinline__ float dot_partial(const float4& a0, const float4& a1, const float4& a2,
                                             const float4& b0, const float4& b1, const float4& b2) {
    float a = a0.x * b0.x;
    a = fmaf(a0.y, b0.y, a); a = fmaf(a0.z, b0.z, a); a = fmaf(a0.w, b0.w, a);
    float c = a1.x * b1.x;
    c = fmaf(a1.y, b1.y, c); c = fmaf(a1.z, b1.z, c); c = fmaf(a1.w, b1.w, c);
    float e = a2.x * b2.x;
    e = fmaf(a2.y, b2.y, e); e = fmaf(a2.z, b2.z, e); e = fmaf(a2.w, b2.w, e);
    return a + c + e;
}

__global__ __launch_bounds__(THREADS, 6)
void sg_loss_kernel(const float* __restrict__ u_w,
                    const float* __restrict__ v_w,
                    const int*   __restrict__ pos_u,
                    const int*   __restrict__ pos_v,
                    const int*   __restrict__ neg_v,
                    float* __restrict__ out) {
    const int warp = threadIdx.x >> 5;
    const int lane = threadIdx.x & 31;
    const int b = blockIdx.x * WARPS_PER_BLOCK + warp;

    const bool has2 = lane < (NF4 - 64);   // lanes 0..10 hold the 3rd float4

    // negative indices live in lanes 0..9; broadcast on demand (saves 10 regs)
    int nidx = 0;
    if (lane < KNEG) nidx = neg_v[b * KNEG + lane];
    const int pvi = pos_v[b];

    // ---- gather emb_u (evict-first: single use, keep v-table in L2) ----
    const float4* u_row = reinterpret_cast<const float4*>(u_w + (long long)pos_u[b] * DIM);
    const float4 u0 = __ldcs(u_row + lane);
    const float4 u1 = __ldcs(u_row + lane + 32);
    float4 u2 = make_float4(0.f, 0.f, 0.f, 0.f);
    if (has2) u2 = __ldcs(u_row + lane + 64);

    float lane_loss = 0.f;

    // ================= batch 0: rows 0..5 =================
    {
        float p[NB0];
#pragma unroll
        for (int j = 0; j < NB0; j++) {
            const int idx = (j == 0) ? pvi : __shfl_sync(0xffffffffu, nidx, j - 1);
            const float4* v_row = reinterpret_cast<const float4*>(v_w + (long long)idx * DIM);
            const float4 v0 = __ldcg(v_row + lane);
            const float4 v1 = __ldcg(v_row + lane + 32);
            float4 v2 = make_float4(0.f, 0.f, 0.f, 0.f);
            if (has2) v2 = __ldcg(v_row + lane + 64);
            p[j] = dot_partial(u0, u1, u2, v0, v1, v2);
        }
#pragma unroll
        for (int off = 16; off; off >>= 1)
#pragma unroll
            for (int j = 0; j < NB0; j++)
                p[j] += __shfl_xor_sync(0xffffffffu, p[j], off);

        // lane j owns row j
        float sel = 0.f;
#pragma unroll
        for (int j = 0; j < NB0; j++) if (lane == j) sel = p[j];
        if (lane < NB0) {
            float s = fminf(fmaxf(sel, -10.f), 10.f);
            lane_loss += softplus_fast((lane == 0) ? -s : s);
        }
    }

    // ================= batch 1: rows 6..10 =================
    {
        float p[NB1];
#pragma unroll
        for (int j = 0; j < NB1; j++) {
            const int idx = __shfl_sync(0xffffffffu, nidx, NB0 - 1 + j);
            const float4* v_row = reinterpret_cast<const float4*>(v_w + (long long)idx * DIM);
            const float4 v0 = __ldcg(v_row + lane);
            const float4 v1 = __ldcg(v_row + lane + 32);
            float4 v2 = make_float4(0.f, 0.f, 0.f, 0.f);
            if (has2) v2 = __ldcg(v_row + lane + 64);
            p[j] = dot_partial(u0, u1, u2, v0, v1, v2);
        }
#pragma unroll
        for (int off = 16; off; off >>= 1)
#pragma unroll
            for (int j = 0; j < NB1; j++)
                p[j] += __shfl_xor_sync(0xffffffffu, p[j], off);

        float sel = 0.f;
#pragma unroll
        for (int j = 0; j < NB1; j++) if (lane == j) sel = p[j];
        if (lane < NB1) {
            float s = fminf(fmaxf(sel, -10.f), 10.f);
            lane_loss += softplus_fast(s);
        }
    }

    // ---- sum the per-lane losses across the warp ----
#pragma unroll
    for (int off = 16; off; off >>= 1)
        lane_loss += __shfl_xor_sync(0xffffffffu, lane_loss, off);

    __shared__ float sloss[WARPS_PER_BLOCK];
    if (lane == 0) sloss[warp] = lane_loss;
    __syncthreads();

    __shared__ unsigned s_is_last;
    if (threadIdx.x == 0) {
        float t = 0.f;
#pragma unroll
        for (int i = 0; i < WARPS_PER_BLOCK; i++) t += sloss[i];
        g_partials[blockIdx.x] = t;
        __threadfence();
        unsigned prev = atomicAdd(&g_count, 1u);
        s_is_last = (prev == (unsigned)(gridDim.x - 1));
    }
    __syncthreads();

    // ---- last block reduces all partials (deterministic fixed order) ----
    if (s_is_last) {
        __threadfence();
        const float4* pp = reinterpret_cast<const float4*>(g_partials);
        float t = 0.f;
#pragma unroll
        for (int i = 0; i < (NBLOCKS / 4) / THREADS; i++) {   // 8 float4 per thread
            float4 v = pp[threadIdx.x + i * THREADS];
            t += (v.x + v.y) + (v.z + v.w);
        }
#pragma unroll
        for (int off = 16; off; off >>= 1)
            t += __shfl_xor_sync(0xffffffffu, t, off);

        __shared__ float sred[WARPS_PER_BLOCK];
        if (lane == 0) sred[warp] = t;
        __syncthreads();
        if (threadIdx.x == 0) {
            float total = 0.f;
#pragma unroll
            for (int i = 0; i < WARPS_PER_BLOCK; i++) total += sred[i];
            out[0] = total * (1.0f / (float)BATCH);
            g_count = 0;   // reset for next graph replay
        }
    }
}

extern "C" void kernel_launch(void* const* d_in, const int* in_sizes, int n_in,
                              void* d_out, int out_size) {
    const float* u_w   = (const float*)d_in[0];
    const float* v_w   = (const float*)d_in[1];
    const int*   pos_u = (const int*)  d_in[2];
    const int*   pos_v = (const int*)  d_in[3];
    const int*   neg_v = (const int*)  d_in[4];
    float* out = (float*)d_out;

    sg_loss_kernel<<<NBLOCKS, THREADS>>>(u_w, v_w, pos_u, pos_v, neg_v, out);
}